// round 11
// baseline (speedup 1.0000x reference)
#include <cuda_runtime.h>
#include <cuda_fp16.h>
#include <math.h>
#include <stdint.h>

// Problem constants
#define T_TOK  8192
#define H_DIM  1024
#define F_DIM  2048
#define N_EXP  8
#define NPAIR  16384

#define OUT_ELEMS  (T_TOK * H_DIM)
#define RL_OFFSET  OUT_ELEMS

// ---------------- device scratch (static: allocation rules) ----------------
__device__ __half g_xh[(size_t)T_TOK * H_DIM];
__device__ __half g_w1h[(size_t)N_EXP * F_DIM * H_DIM];
__device__ __half g_w3h[(size_t)N_EXP * F_DIM * H_DIM];
__device__ __half g_w2h[(size_t)N_EXP * H_DIM * F_DIM];
__device__ __half g_gatedh[(size_t)NPAIR * F_DIM];
__device__ float  g_y[(size_t)NPAIR * H_DIM];
__device__ int    g_bucket[N_EXP * NPAIR];
__device__ int    g_cnt[N_EXP];
__device__ float  g_wpair[NPAIR];

// =================== PTX helpers (baseline sm_80-class PTX) ===================
__device__ __forceinline__ uint32_t smem_u32(const void* p) {
    uint32_t a;
    asm("{ .reg .u64 t; cvta.to.shared.u64 t, %1; cvt.u32.u64 %0, t; }" : "=r"(a) : "l"(p));
    return a;
}
#define CP16(dst, src) asm volatile("cp.async.cg.shared.global [%0], [%1], 16;" :: "r"(dst), "l"(src))
#define CPCOMMIT()     asm volatile("cp.async.commit_group;")
#define CPWAIT(n)      asm volatile("cp.async.wait_group %0;" :: "n"(n))

__device__ __forceinline__ void ldm_x4(uint32_t* r, uint32_t addr) {
    asm volatile("ldmatrix.sync.aligned.m8n8.x4.shared.b16 {%0,%1,%2,%3}, [%4];"
        : "=r"(r[0]), "=r"(r[1]), "=r"(r[2]), "=r"(r[3]) : "r"(addr));
}
__device__ __forceinline__ void mma16(float* c, const uint32_t* a, uint32_t b0, uint32_t b1) {
    asm volatile(
        "mma.sync.aligned.m16n8k16.row.col.f32.f16.f16.f32 "
        "{%0,%1,%2,%3}, {%4,%5,%6,%7}, {%8,%9}, {%0,%1,%2,%3};"
        : "+f"(c[0]), "+f"(c[1]), "+f"(c[2]), "+f"(c[3])
        : "r"(a[0]), "r"(a[1]), "r"(a[2]), "r"(a[3]), "r"(b0), "r"(b1));
}
// smem tile rows are 128B (64 halfs = BK chunk); phys(row, 16B-unit u) =
// row*128 + ((u ^ (row&7))<<4)  -> conflict-free cp.async + ldmatrix

// =================== kernel 0: zero counters ===================
__global__ void zero_cnt_kernel() {
    if (threadIdx.x < N_EXP) g_cnt[threadIdx.x] = 0;
}

// =================== fused f32 -> f16 (rne) bulk convert ===================
#define NX4 ((T_TOK * H_DIM) / 4)
#define NW4 ((N_EXP * F_DIM * H_DIM) / 4)
#define NCVT (NX4 + 3 * NW4)

__global__ void f2h_all_kernel(const float4* __restrict__ x,
                               const float4* __restrict__ w1,
                               const float4* __restrict__ w3,
                               const float4* __restrict__ w2,
                               uint2* __restrict__ xh, uint2* __restrict__ w1h,
                               uint2* __restrict__ w3h, uint2* __restrict__ w2h) {
    int i = blockIdx.x * blockDim.x + threadIdx.x;
    if (i >= NCVT) return;
    const float4* s;
    uint2* d;
    int j;
    if (i < NX4)               { s = x;  d = xh;  j = i; }
    else if (i < NX4 + NW4)    { s = w1; d = w1h; j = i - NX4; }
    else if (i < NX4 + 2*NW4)  { s = w3; d = w3h; j = i - NX4 - NW4; }
    else                       { s = w2; d = w2h; j = i - NX4 - 2*NW4; }
    float4 v = s[j];
    __half2 h0 = __floats2half2_rn(v.x, v.y);
    __half2 h1 = __floats2half2_rn(v.z, v.w);
    uint2 o;
    o.x = *reinterpret_cast<uint32_t*>(&h0);
    o.y = *reinterpret_cast<uint32_t*>(&h1);
    d[j] = o;
}

// =================== kernel 1: router (f32, exact) ===================
__global__ void router_kernel(const float* __restrict__ x,
                              const float* __restrict__ gw,
                              float* __restrict__ rlogits) {
    int warp = (blockIdx.x * blockDim.x + threadIdx.x) >> 5;
    int lane = threadIdx.x & 31;
    if (warp >= T_TOK) return;

    const float* xr = x + (size_t)warp * H_DIM;
    float xv[32];
#pragma unroll
    for (int i = 0; i < 32; i++) xv[i] = xr[i * 32 + lane];

    float l[N_EXP];
#pragma unroll
    for (int e = 0; e < N_EXP; e++) {
        const float* g = gw + e * H_DIM;
        float s = 0.f;
#pragma unroll
        for (int i = 0; i < 32; i++) s += xv[i] * g[i * 32 + lane];
#pragma unroll
        for (int o = 16; o; o >>= 1) s += __shfl_xor_sync(0xffffffffu, s, o);
        l[e] = s;
    }

    if (lane == 0) {
#pragma unroll
        for (int e = 0; e < N_EXP; e++) rlogits[(size_t)warp * N_EXP + e] = l[e];

        int i0 = 0;
#pragma unroll
        for (int e = 1; e < N_EXP; e++) if (l[e] > l[i0]) i0 = e;
        int i1 = (i0 == 0) ? 1 : 0;
#pragma unroll
        for (int e = 0; e < N_EXP; e++) if (e != i0 && l[e] > l[i1]) i1 = e;

        float e1 = expf(l[i1] - l[i0]);
        float w0 = 1.f / (1.f + e1);
        float w1 = e1 / (1.f + e1);

        int p0 = warp * 2, p1 = warp * 2 + 1;
        g_wpair[p0] = w0;
        g_wpair[p1] = w1;
        int pos0 = atomicAdd(&g_cnt[i0], 1);
        g_bucket[i0 * NPAIR + pos0] = p0;
        int pos1 = atomicAdd(&g_cnt[i1], 1);
        g_bucket[i1 * NPAIR + pos1] = p1;
    }
}

// =================== kernel 2: GEMM1 fp16 (256x64, BK=64, 3-stage) ==========
// CTA: 256 pairs x 64 F-cols, 256 threads = 8 warps (4m x 2n),
// warp tile 64x32 DUAL accum (acc1+acc3 = 128 f32/thread).
// stage (48KB): A 256x128B @0, B1 64x128B @32K, B3 @40K. 3 stages, one sync.
#define G1_STAGE 49152
#define G1_SMEM  (1024 + 3 * G1_STAGE)
#define G1_NCH   (H_DIM / 64)    // 16

__global__ __launch_bounds__(256, 1) void gemm1_h() {
    int e = blockIdx.z;
    int nrows = g_cnt[e];
    int mbase = blockIdx.y * 256;
    if (mbase >= nrows) return;
    int fbase = blockIdx.x * 64;

    extern __shared__ char smem[];
    int* rowpair = (int*)smem;
    uint32_t sb = smem_u32(smem + 1024);

    int tid = threadIdx.x;
    int wid = tid >> 5, lane = tid & 31;
    int g = lane >> 2, tig = lane & 3;
    int wm = wid & 3, wn = wid >> 2;          // 4m x 2n warp grid

    rowpair[tid] = (mbase + tid < nrows) ? g_bucket[e * NPAIR + mbase + tid] : -1;
    __syncthreads();

    // cp.async mapping: trow = tid>>3 (0..31), tu = tid&7; 8 A rows + 2+2 B rows
    int trow = tid >> 3, tu = tid & 7;
    const __half* aptr[8];
    uint32_t dstA0 = (uint32_t)(trow * 128 + ((tu ^ (trow & 7)) << 4));
#pragma unroll
    for (int q = 0; q < 8; q++) {
        int rq = q * 32 + trow;
        int rp = rowpair[rq];
        int tok = ((rp >= 0) ? rp : rowpair[0]) >> 1;
        aptr[q] = g_xh + (size_t)tok * H_DIM + tu * 8;
    }
    const __half* b1p = g_w1h + ((size_t)e * F_DIM + fbase + trow) * H_DIM + tu * 8;
    const __half* b3p = g_w3h + ((size_t)e * F_DIM + fbase + trow) * H_DIM + tu * 8;

    auto load_chunk = [&](int c, int s) {
        uint32_t base = sb + s * G1_STAGE;
        int ko = c * 64;
#pragma unroll
        for (int q = 0; q < 8; q++) CP16(base + dstA0 + q * 4096, aptr[q] + ko);
#pragma unroll
        for (int j = 0; j < 2; j++) {
            CP16(base + 32768 + dstA0 + j * 4096, b1p + j * 32 * H_DIM + ko);
            CP16(base + 40960 + dstA0 + j * 4096, b3p + j * 32 * H_DIM + ko);
        }
        CPCOMMIT();
    };

    int lro = ((lane >> 3) & 1) * 8 + (lane & 7);
    int hi = lane >> 4;

    float acc1[4][4][4] = {}, acc3[4][4][4] = {};

    load_chunk(0, 0);
    load_chunk(1, 1);
    for (int c = 0; c < G1_NCH; c++) {
        CPWAIT(1);                 // chunk c landed
        __syncthreads();           // publish chunk c; chunk c-1 stage now dead
        if (c + 2 < G1_NCH) load_chunk(c + 2, (c + 2) % 3);
        else                CPCOMMIT();

        uint32_t aT = sb + (c % 3) * G1_STAGE;
        uint32_t b1T = aT + 32768, b3T = aT + 40960;
#pragma unroll
        for (int kk = 0; kk < 4; kk++) {
            uint32_t af[4][4];
#pragma unroll
            for (int mf = 0; mf < 4; mf++) {
                int lr = wm * 64 + mf * 16 + lro;
                ldm_x4(af[mf], aT + lr * 128 + ((((kk * 2 + hi)) ^ (lr & 7)) << 4));
            }
            uint32_t bf1[2][4], bf3[2][4];
#pragma unroll
            for (int j = 0; j < 2; j++) {
                int lr = wn * 32 + j * 16 + lro;
                uint32_t ao = lr * 128 + ((((kk * 2 + hi)) ^ (lr & 7)) << 4);
                ldm_x4(bf1[j], b1T + ao);
                ldm_x4(bf3[j], b3T + ao);
            }
#pragma unroll
            for (int mf = 0; mf < 4; mf++)
#pragma unroll
                for (int nf = 0; nf < 4; nf++) {
                    int j = nf >> 1, w = nf & 1;
                    mma16(acc1[mf][nf], af[mf], bf1[j][w], bf1[j][w + 2]);
                    mma16(acc3[mf][nf], af[mf], bf3[j][w], bf3[j][w + 2]);
                }
        }
    }

    // epilogue: silu(acc1)*acc3 -> g_gatedh (fp16)
#pragma unroll
    for (int mf = 0; mf < 4; mf++) {
#pragma unroll
        for (int hh = 0; hh < 2; hh++) {
            int row = wm * 64 + mf * 16 + g + hh * 8;
            int p = rowpair[row];
            if (p < 0) continue;
            __half* dst = g_gatedh + (size_t)p * F_DIM + fbase;
#pragma unroll
            for (int nf = 0; nf < 4; nf++) {
                int col = wn * 32 + nf * 8 + tig * 2;
                float c0 = acc1[mf][nf][hh * 2 + 0];
                float c1 = acc1[mf][nf][hh * 2 + 1];
                float g0 = acc3[mf][nf][hh * 2 + 0];
                float g1 = acc3[mf][nf][hh * 2 + 1];
                float o0 = c0 / (1.f + expf(-c0)) * g0;
                float o1 = c1 / (1.f + expf(-c1)) * g1;
                *(__half2*)(dst + col) = __floats2half2_rn(o0, o1);
            }
        }
    }
}

// =================== kernel 3: GEMM2 fp16 (128x256, BK=64, 3-stage) =========
// CTA: 128 pairs x 256 H-cols, K = F_DIM. 256 threads = 8 warps (2m x 4n),
// warp tile 64x64 (acc = 128 f32/thread).
// stage (48KB): A 128x128B @0, B 256x128B @16K. 3 stages, one sync.
#define G2_STAGE 49152
#define G2_SMEM  (1024 + 3 * G2_STAGE)
#define G2_NCH   (F_DIM / 64)    // 32

__global__ __launch_bounds__(256, 1) void gemm2_h() {
    int e = blockIdx.z;
    int nrows = g_cnt[e];
    int mbase = blockIdx.y * 128;
    if (mbase >= nrows) return;
    int hbase = blockIdx.x * 256;

    extern __shared__ char smem[];
    int* rowpair = (int*)smem;
    uint32_t sb = smem_u32(smem + 1024);

    int tid = threadIdx.x;
    int wid = tid >> 5, lane = tid & 31;
    int g = lane >> 2, tig = lane & 3;
    int wm = wid & 1, wn = wid >> 1;          // 2m x 4n warp grid

    if (tid < 128) {
        int r = mbase + tid;
        rowpair[tid] = (r < nrows) ? g_bucket[e * NPAIR + r] : -1;
    }
    __syncthreads();

    int trow = tid >> 3, tu = tid & 7;
    const __half* aptr[4];
    uint32_t dst0 = (uint32_t)(trow * 128 + ((tu ^ (trow & 7)) << 4));
#pragma unroll
    for (int q = 0; q < 4; q++) {
        int rq = q * 32 + trow;
        int rp = rowpair[rq];
        int pr = (rp >= 0) ? rp : rowpair[0];
        aptr[q] = g_gatedh + (size_t)pr * F_DIM + tu * 8;
    }
    const __half* bp = g_w2h + ((size_t)e * H_DIM + hbase + trow) * F_DIM + tu * 8;

    auto load_chunk = [&](int c, int s) {
        uint32_t base = sb + s * G2_STAGE;
        int ko = c * 64;
#pragma unroll
        for (int q = 0; q < 4; q++) CP16(base + dst0 + q * 4096, aptr[q] + ko);
#pragma unroll
        for (int q = 0; q < 8; q++)
            CP16(base + 16384 + dst0 + q * 4096, bp + (size_t)q * 32 * F_DIM + ko);
        CPCOMMIT();
    };

    int lro = ((lane >> 3) & 1) * 8 + (lane & 7);
    int hi = lane >> 4;

    float acc[4][8][4] = {};

    load_chunk(0, 0);
    load_chunk(1, 1);
    for (int c = 0; c < G2_NCH; c++) {
        CPWAIT(1);
        __syncthreads();
        if (c + 2 < G2_NCH) load_chunk(c + 2, (c + 2) % 3);
        else                CPCOMMIT();

        uint32_t aT = sb + (c % 3) * G2_STAGE;
        uint32_t bT = aT + 16384;
#pragma unroll
        for (int kk = 0; kk < 4; kk++) {
            uint32_t af[4][4];
#pragma unroll
            for (int mf = 0; mf < 4; mf++) {
                int lr = wm * 64 + mf * 16 + lro;
                ldm_x4(af[mf], aT + lr * 128 + ((((kk * 2 + hi)) ^ (lr & 7)) << 4));
            }
            uint32_t bf[4][4];
#pragma unroll
            for (int j = 0; j < 4; j++) {
                int lr = wn * 64 + j * 16 + lro;
                ldm_x4(bf[j], bT + lr * 128 + ((((kk * 2 + hi)) ^ (lr & 7)) << 4));
            }
#pragma unroll
            for (int mf = 0; mf < 4; mf++)
#pragma unroll
                for (int nf = 0; nf < 8; nf++) {
                    int j = nf >> 1, w = nf & 1;
                    mma16(acc[mf][nf], af[mf], bf[j][w], bf[j][w + 2]);
                }
        }
    }

#pragma unroll
    for (int mf = 0; mf < 4; mf++) {
#pragma unroll
        for (int hh = 0; hh < 2; hh++) {
            int row = wm * 64 + mf * 16 + g + hh * 8;
            int p = rowpair[row];
            if (p < 0) continue;
            float* dst = g_y + (size_t)p * H_DIM + hbase;
#pragma unroll
            for (int nf = 0; nf < 8; nf++) {
                int col = wn * 64 + nf * 8 + tig * 2;
                float2 o;
                o.x = acc[mf][nf][hh * 2 + 0];
                o.y = acc[mf][nf][hh * 2 + 1];
                *(float2*)(dst + col) = o;
            }
        }
    }
}

// =================== kernel 4: weighted combine ===================
__global__ void combine_kernel(float* __restrict__ out) {
    int idx = blockIdx.x * blockDim.x + threadIdx.x;
    if (idx >= T_TOK * H_DIM / 4) return;
    int t = idx / (H_DIM / 4);
    int h4 = idx - t * (H_DIM / 4);
    float w0 = g_wpair[2 * t];
    float w1 = g_wpair[2 * t + 1];
    float4 a = *(const float4*)(g_y + (size_t)(2 * t) * H_DIM + h4 * 4);
    float4 b = *(const float4*)(g_y + (size_t)(2 * t + 1) * H_DIM + h4 * 4);
    float4 o;
    o.x = w0 * a.x + w1 * b.x;
    o.y = w0 * a.y + w1 * b.y;
    o.z = w0 * a.z + w1 * b.z;
    o.w = w0 * a.w + w1 * b.w;
    ((float4*)out)[idx] = o;
}

// =================== launch ===================
extern "C" void kernel_launch(void* const* d_in, const int* in_sizes, int n_in,
                              void* d_out, int out_size) {
    const float* hidden = (const float*)d_in[0];
    const float* gate_w = (const float*)d_in[1];
    const float* w1     = (const float*)d_in[2];
    const float* w3     = (const float*)d_in[3];
    const float* w2     = (const float*)d_in[4];
    float* out = (float*)d_out;

    static int attr_done = 0;
    if (!attr_done) {
        cudaFuncSetAttribute(gemm1_h, cudaFuncAttributeMaxDynamicSharedMemorySize, G1_SMEM);
        cudaFuncSetAttribute(gemm2_h, cudaFuncAttributeMaxDynamicSharedMemorySize, G2_SMEM);
        attr_done = 1;
    }

    static void *p_xh = nullptr, *p_w1h, *p_w3h, *p_w2h;
    if (!p_xh) {
        cudaGetSymbolAddress(&p_xh, g_xh);
        cudaGetSymbolAddress(&p_w1h, g_w1h);
        cudaGetSymbolAddress(&p_w3h, g_w3h);
        cudaGetSymbolAddress(&p_w2h, g_w2h);
    }

    zero_cnt_kernel<<<1, 32>>>();
    f2h_all_kernel<<<(NCVT + 255) / 256, 256>>>(
        (const float4*)hidden, (const float4*)w1, (const float4*)w3, (const float4*)w2,
        (uint2*)p_xh, (uint2*)p_w1h, (uint2*)p_w3h, (uint2*)p_w2h);
    router_kernel<<<T_TOK / 8, 256>>>(hidden, gate_w, out + RL_OFFSET);
    // worst case one expert owns all NPAIR pairs; extra CTAs exit
    gemm1_h<<<dim3(F_DIM / 64, NPAIR / 256, N_EXP), 256, G1_SMEM>>>();
    gemm2_h<<<dim3(H_DIM / 256, NPAIR / 128, N_EXP), 256, G2_SMEM>>>();
    combine_kernel<<<(T_TOK * H_DIM / 4 + 255) / 256, 256>>>(out);
}

// round 13
// speedup vs baseline: 1.0108x; 1.0108x over previous
#include <cuda_runtime.h>
#include <cuda_fp16.h>
#include <math.h>
#include <stdint.h>

// Problem constants
#define T_TOK  8192
#define H_DIM  1024
#define F_DIM  2048
#define N_EXP  8
#define NPAIR  16384

#define OUT_ELEMS  (T_TOK * H_DIM)
#define RL_OFFSET  OUT_ELEMS

// ---------------- device scratch (static: allocation rules) ----------------
__device__ __half g_xh[(size_t)T_TOK * H_DIM];
__device__ __half g_w1h[(size_t)N_EXP * F_DIM * H_DIM];
__device__ __half g_w3h[(size_t)N_EXP * F_DIM * H_DIM];
__device__ __half g_w2h[(size_t)N_EXP * H_DIM * F_DIM];
__device__ __half g_gatedh[(size_t)NPAIR * F_DIM];
__device__ float  g_y[(size_t)NPAIR * H_DIM];
__device__ int    g_bucket[N_EXP * NPAIR];
__device__ int    g_cnt[N_EXP];
__device__ float  g_wpair[NPAIR];

// =================== PTX helpers (baseline sm_80-class PTX) ===================
__device__ __forceinline__ uint32_t smem_u32(const void* p) {
    uint32_t a;
    asm("{ .reg .u64 t; cvta.to.shared.u64 t, %1; cvt.u32.u64 %0, t; }" : "=r"(a) : "l"(p));
    return a;
}
#define CP16(dst, src) asm volatile("cp.async.cg.shared.global [%0], [%1], 16;" :: "r"(dst), "l"(src))
#define CPCOMMIT()     asm volatile("cp.async.commit_group;")
#define CPWAIT(n)      asm volatile("cp.async.wait_group %0;" :: "n"(n))

__device__ __forceinline__ void ldm_x4(uint32_t* r, uint32_t addr) {
    asm volatile("ldmatrix.sync.aligned.m8n8.x4.shared.b16 {%0,%1,%2,%3}, [%4];"
        : "=r"(r[0]), "=r"(r[1]), "=r"(r[2]), "=r"(r[3]) : "r"(addr));
}
__device__ __forceinline__ void mma16(float* c, const uint32_t* a, uint32_t b0, uint32_t b1) {
    asm volatile(
        "mma.sync.aligned.m16n8k16.row.col.f32.f16.f16.f32 "
        "{%0,%1,%2,%3}, {%4,%5,%6,%7}, {%8,%9}, {%0,%1,%2,%3};"
        : "+f"(c[0]), "+f"(c[1]), "+f"(c[2]), "+f"(c[3])
        : "r"(a[0]), "r"(a[1]), "r"(a[2]), "r"(a[3]), "r"(b0), "r"(b1));
}
// smem tile rows are 128B (64 halfs = BK chunk); phys(row, 16B-unit u) =
// row*128 + ((u ^ (row&7))<<4)  -> conflict-free cp.async + ldmatrix.
// NOTE: all ldmatrix fragment rows have (row&7) == (lane&7), so the XOR term
// is a single per-kk value shared by every fragment address in the warp.

// =================== kernel 0: zero counters ===================
__global__ void zero_cnt_kernel() {
    if (threadIdx.x < N_EXP) g_cnt[threadIdx.x] = 0;
}

// =================== fused f32 -> f16 (rne) bulk convert ===================
#define NX4 ((T_TOK * H_DIM) / 4)
#define NW4 ((N_EXP * F_DIM * H_DIM) / 4)
#define NCVT (NX4 + 3 * NW4)

__global__ void f2h_all_kernel(const float4* __restrict__ x,
                               const float4* __restrict__ w1,
                               const float4* __restrict__ w3,
                               const float4* __restrict__ w2,
                               uint2* __restrict__ xh, uint2* __restrict__ w1h,
                               uint2* __restrict__ w3h, uint2* __restrict__ w2h) {
    int i = blockIdx.x * blockDim.x + threadIdx.x;
    if (i >= NCVT) return;
    const float4* s;
    uint2* d;
    int j;
    if (i < NX4)               { s = x;  d = xh;  j = i; }
    else if (i < NX4 + NW4)    { s = w1; d = w1h; j = i - NX4; }
    else if (i < NX4 + 2*NW4)  { s = w3; d = w3h; j = i - NX4 - NW4; }
    else                       { s = w2; d = w2h; j = i - NX4 - 2*NW4; }
    float4 v = s[j];
    __half2 h0 = __floats2half2_rn(v.x, v.y);
    __half2 h1 = __floats2half2_rn(v.z, v.w);
    uint2 o;
    o.x = *reinterpret_cast<uint32_t*>(&h0);
    o.y = *reinterpret_cast<uint32_t*>(&h1);
    d[j] = o;
}

// =================== kernel 1: router (f32, exact) ===================
__global__ void router_kernel(const float* __restrict__ x,
                              const float* __restrict__ gw,
                              float* __restrict__ rlogits) {
    int warp = (blockIdx.x * blockDim.x + threadIdx.x) >> 5;
    int lane = threadIdx.x & 31;
    if (warp >= T_TOK) return;

    const float* xr = x + (size_t)warp * H_DIM;
    float xv[32];
#pragma unroll
    for (int i = 0; i < 32; i++) xv[i] = xr[i * 32 + lane];

    float l[N_EXP];
#pragma unroll
    for (int e = 0; e < N_EXP; e++) {
        const float* g = gw + e * H_DIM;
        float s = 0.f;
#pragma unroll
        for (int i = 0; i < 32; i++) s += xv[i] * g[i * 32 + lane];
#pragma unroll
        for (int o = 16; o; o >>= 1) s += __shfl_xor_sync(0xffffffffu, s, o);
        l[e] = s;
    }

    if (lane == 0) {
#pragma unroll
        for (int e = 0; e < N_EXP; e++) rlogits[(size_t)warp * N_EXP + e] = l[e];

        int i0 = 0;
#pragma unroll
        for (int e = 1; e < N_EXP; e++) if (l[e] > l[i0]) i0 = e;
        int i1 = (i0 == 0) ? 1 : 0;
#pragma unroll
        for (int e = 0; e < N_EXP; e++) if (e != i0 && l[e] > l[i1]) i1 = e;

        float e1 = expf(l[i1] - l[i0]);
        float w0 = 1.f / (1.f + e1);
        float w1 = e1 / (1.f + e1);

        int p0 = warp * 2, p1 = warp * 2 + 1;
        g_wpair[p0] = w0;
        g_wpair[p1] = w1;
        int pos0 = atomicAdd(&g_cnt[i0], 1);
        g_bucket[i0 * NPAIR + pos0] = p0;
        int pos1 = atomicAdd(&g_cnt[i1], 1);
        g_bucket[i1 * NPAIR + pos1] = p1;
    }
}

// =================== kernel 2: GEMM1 fp16 (256x64, BK=64, 3-stage) ==========
// CTA: 256 pairs x 64 F-cols. D1 = X W1^T, D3 = X W3^T, silu fuse -> g_gatedh.
// 512 threads = 16 warps (8m x 2n), warp tile 32x32 (dual accum).
// stage (48KB): A 256x128B @0, B1 64x128B @32K, B3 @40K. 3 stages, one sync.
#define G1_STAGE 49152
#define G1_SMEM  (1024 + 3 * G1_STAGE)
#define G1_NCH   (H_DIM / 64)    // 16

__global__ __launch_bounds__(512, 1) void gemm1_h() {
    int e = blockIdx.z;
    int nrows = g_cnt[e];
    int mbase = blockIdx.y * 256;
    if (mbase >= nrows) return;
    int fbase = blockIdx.x * 64;

    extern __shared__ char smem[];
    int* rowpair = (int*)smem;
    uint32_t sb = smem_u32(smem + 1024);

    int tid = threadIdx.x;
    int wid = tid >> 5, lane = tid & 31;
    int g = lane >> 2, tig = lane & 3;
    int wm = wid & 7, wn = wid >> 3;          // 8 x 2 warp grid

    if (tid < 256) {
        int r = mbase + tid;
        rowpair[tid] = (r < nrows) ? g_bucket[e * NPAIR + r] : -1;
    }
    __syncthreads();

    // cp.async mapping: trow = tid>>3 (0..63), tu = tid&7
    int trow = tid >> 3, tu = tid & 7;
    const __half* aptr[4];
    uint32_t dstA[4];
#pragma unroll
    for (int q = 0; q < 4; q++) {
        int rq = q * 64 + trow;
        int rp = rowpair[rq];
        int tok = ((rp >= 0) ? rp : rowpair[0]) >> 1;
        aptr[q] = g_xh + (size_t)tok * H_DIM + tu * 8;
        dstA[q] = (uint32_t)(rq * 128 + ((tu ^ (rq & 7)) << 4));
    }
    const __half* b1p = g_w1h + ((size_t)e * F_DIM + fbase + trow) * H_DIM + tu * 8;
    const __half* b3p = g_w3h + ((size_t)e * F_DIM + fbase + trow) * H_DIM + tu * 8;
    uint32_t dstB = (uint32_t)(trow * 128 + ((tu ^ (trow & 7)) << 4));

    auto load_chunk = [&](int c, int s) {
        uint32_t base = sb + s * G1_STAGE;
        int ko = c * 64;
#pragma unroll
        for (int q = 0; q < 4; q++) CP16(base + dstA[q], aptr[q] + ko);
        CP16(base + 32768 + dstB, b1p + ko);
        CP16(base + 40960 + dstB, b3p + ko);
        CPCOMMIT();
    };

    int lro = ((lane >> 3) & 1) * 8 + (lane & 7);
    int hi = lane >> 4;
    int s7 = lane & 7;

    // hoisted ldmatrix address components (all frag rows have row&7 == s7)
    uint32_t xoff[4];
#pragma unroll
    for (int kk = 0; kk < 4; kk++) xoff[kk] = (uint32_t)(((kk * 2 + hi) ^ s7) << 4);
    uint32_t aro[2], bro[2];
#pragma unroll
    for (int mf = 0; mf < 2; mf++) aro[mf] = (uint32_t)((wm * 32 + mf * 16 + lro) * 128);
#pragma unroll
    for (int j = 0; j < 2; j++)    bro[j]  = (uint32_t)((wn * 32 + j * 16 + lro) * 128);

    float acc1[2][4][4] = {}, acc3[2][4][4] = {};

    load_chunk(0, 0);
    load_chunk(1, 1);
    for (int c = 0; c < G1_NCH; c++) {
        CPWAIT(1);                 // chunk c landed
        __syncthreads();           // publish chunk c; chunk c-1 stage now dead
        if (c + 2 < G1_NCH) load_chunk(c + 2, (c + 2) % 3);
        else                CPCOMMIT();   // keep group accounting uniform

        uint32_t aT = sb + (c % 3) * G1_STAGE;
#pragma unroll
        for (int kk = 0; kk < 4; kk++) {
            uint32_t aX  = aT + xoff[kk];
            uint32_t b1X = aX + 32768;
            uint32_t b3X = aX + 40960;
            uint32_t af[2][4];
#pragma unroll
            for (int mf = 0; mf < 2; mf++) ldm_x4(af[mf], aX + aro[mf]);
            uint32_t bf1[2][4], bf3[2][4];
#pragma unroll
            for (int j = 0; j < 2; j++) {
                ldm_x4(bf1[j], b1X + bro[j]);
                ldm_x4(bf3[j], b3X + bro[j]);
            }
#pragma unroll
            for (int mf = 0; mf < 2; mf++)
#pragma unroll
                for (int nf = 0; nf < 4; nf++) {
                    int j = nf >> 1, w = nf & 1;
                    mma16(acc1[mf][nf], af[mf], bf1[j][w], bf1[j][w + 2]);
                    mma16(acc3[mf][nf], af[mf], bf3[j][w], bf3[j][w + 2]);
                }
        }
    }

    // epilogue: silu(acc1)*acc3 -> g_gatedh (fp16)
#pragma unroll
    for (int mf = 0; mf < 2; mf++) {
#pragma unroll
        for (int hh = 0; hh < 2; hh++) {
            int row = wm * 32 + mf * 16 + g + hh * 8;
            int p = rowpair[row];
            if (p < 0) continue;
            __half* dst = g_gatedh + (size_t)p * F_DIM + fbase;
#pragma unroll
            for (int nf = 0; nf < 4; nf++) {
                int col = wn * 32 + nf * 8 + tig * 2;
                float c0 = acc1[mf][nf][hh * 2 + 0];
                float c1 = acc1[mf][nf][hh * 2 + 1];
                float g0 = acc3[mf][nf][hh * 2 + 0];
                float g1 = acc3[mf][nf][hh * 2 + 1];
                float o0 = c0 / (1.f + expf(-c0)) * g0;
                float o1 = c1 / (1.f + expf(-c1)) * g1;
                *(__half2*)(dst + col) = __floats2half2_rn(o0, o1);
            }
        }
    }
}

// =================== kernel 3: GEMM2 fp16 (128x256, BK=64, 3-stage) =========
// CTA: 128 pairs x 256 H-cols, K = F_DIM.
// 512 threads = 16 warps (4m x 4n), warp tile 32x64.
// stage (48KB): A 128x128B @0, B 256x128B @16K. 3 stages, single-sync.
#define G2_STAGE 49152
#define G2_SMEM  (1024 + 3 * G2_STAGE)
#define G2_NCH   (F_DIM / 64)    // 32

__global__ __launch_bounds__(512, 1) void gemm2_h() {
    int e = blockIdx.z;
    int nrows = g_cnt[e];
    int mbase = blockIdx.y * 128;
    if (mbase >= nrows) return;
    int hbase = blockIdx.x * 256;

    extern __shared__ char smem[];
    int* rowpair = (int*)smem;
    uint32_t sb = smem_u32(smem + 1024);

    int tid = threadIdx.x;
    int wid = tid >> 5, lane = tid & 31;
    int g = lane >> 2, tig = lane & 3;
    int wm = wid & 3, wn = wid >> 2;          // 4 x 4 warp grid

    if (tid < 128) {
        int r = mbase + tid;
        rowpair[tid] = (r < nrows) ? g_bucket[e * NPAIR + r] : -1;
    }
    __syncthreads();

    int trow = tid >> 3, tu = tid & 7;
    const __half* aptr[2];
    uint32_t dstA[2];
#pragma unroll
    for (int q = 0; q < 2; q++) {
        int rq = q * 64 + trow;
        int rp = rowpair[rq];
        int pr = (rp >= 0) ? rp : rowpair[0];
        aptr[q] = g_gatedh + (size_t)pr * F_DIM + tu * 8;
        dstA[q] = (uint32_t)(rq * 128 + ((tu ^ (rq & 7)) << 4));
    }
    const __half* bptr[4];
    uint32_t dstB[4];
#pragma unroll
    for (int q = 0; q < 4; q++) {
        int rq = q * 64 + trow;
        bptr[q] = g_w2h + ((size_t)e * H_DIM + hbase + rq) * F_DIM + tu * 8;
        dstB[q] = (uint32_t)(rq * 128 + ((tu ^ (rq & 7)) << 4));
    }

    auto load_chunk = [&](int c, int s) {
        uint32_t base = sb + s * G2_STAGE;
        int ko = c * 64;
#pragma unroll
        for (int q = 0; q < 2; q++) CP16(base + dstA[q], aptr[q] + ko);
#pragma unroll
        for (int q = 0; q < 4; q++) CP16(base + 16384 + dstB[q], bptr[q] + ko);
        CPCOMMIT();
    };

    int lro = ((lane >> 3) & 1) * 8 + (lane & 7);
    int hi = lane >> 4;
    int s7 = lane & 7;

    uint32_t xoff[4];
#pragma unroll
    for (int kk = 0; kk < 4; kk++) xoff[kk] = (uint32_t)(((kk * 2 + hi) ^ s7) << 4);
    uint32_t aro[2], bro[4];
#pragma unroll
    for (int mf = 0; mf < 2; mf++) aro[mf] = (uint32_t)((wm * 32 + mf * 16 + lro) * 128);
#pragma unroll
    for (int j = 0; j < 4; j++)    bro[j]  = (uint32_t)((wn * 64 + j * 16 + lro) * 128);

    float acc[2][8][4] = {};

    load_chunk(0, 0);
    load_chunk(1, 1);
    for (int c = 0; c < G2_NCH; c++) {
        CPWAIT(1);
        __syncthreads();
        if (c + 2 < G2_NCH) load_chunk(c + 2, (c + 2) % 3);
        else                CPCOMMIT();

        uint32_t aT = sb + (c % 3) * G2_STAGE;
#pragma unroll
        for (int kk = 0; kk < 4; kk++) {
            uint32_t aX = aT + xoff[kk];
            uint32_t bX = aX + 16384;
            uint32_t af[2][4];
#pragma unroll
            for (int mf = 0; mf < 2; mf++) ldm_x4(af[mf], aX + aro[mf]);
            uint32_t bf[4][4];
#pragma unroll
            for (int j = 0; j < 4; j++) ldm_x4(bf[j], bX + bro[j]);
#pragma unroll
            for (int mf = 0; mf < 2; mf++)
#pragma unroll
                for (int nf = 0; nf < 8; nf++) {
                    int j = nf >> 1, w = nf & 1;
                    mma16(acc[mf][nf], af[mf], bf[j][w], bf[j][w + 2]);
                }
        }
    }

#pragma unroll
    for (int mf = 0; mf < 2; mf++) {
#pragma unroll
        for (int hh = 0; hh < 2; hh++) {
            int row = wm * 32 + mf * 16 + g + hh * 8;
            int p = rowpair[row];
            if (p < 0) continue;
            float* dst = g_y + (size_t)p * H_DIM + hbase;
#pragma unroll
            for (int nf = 0; nf < 8; nf++) {
                int col = wn * 64 + nf * 8 + tig * 2;
                float2 o;
                o.x = acc[mf][nf][hh * 2 + 0];
                o.y = acc[mf][nf][hh * 2 + 1];
                *(float2*)(dst + col) = o;
            }
        }
    }
}

// =================== kernel 4: weighted combine ===================
__global__ void combine_kernel(float* __restrict__ out) {
    int idx = blockIdx.x * blockDim.x + threadIdx.x;
    if (idx >= T_TOK * H_DIM / 4) return;
    int t = idx / (H_DIM / 4);
    int h4 = idx - t * (H_DIM / 4);
    float w0 = g_wpair[2 * t];
    float w1 = g_wpair[2 * t + 1];
    float4 a = *(const float4*)(g_y + (size_t)(2 * t) * H_DIM + h4 * 4);
    float4 b = *(const float4*)(g_y + (size_t)(2 * t + 1) * H_DIM + h4 * 4);
    float4 o;
    o.x = w0 * a.x + w1 * b.x;
    o.y = w0 * a.y + w1 * b.y;
    o.z = w0 * a.z + w1 * b.z;
    o.w = w0 * a.w + w1 * b.w;
    ((float4*)out)[idx] = o;
}

// =================== launch ===================
extern "C" void kernel_launch(void* const* d_in, const int* in_sizes, int n_in,
                              void* d_out, int out_size) {
    const float* hidden = (const float*)d_in[0];
    const float* gate_w = (const float*)d_in[1];
    const float* w1     = (const float*)d_in[2];
    const float* w3     = (const float*)d_in[3];
    const float* w2     = (const float*)d_in[4];
    float* out = (float*)d_out;

    static int attr_done = 0;
    if (!attr_done) {
        cudaFuncSetAttribute(gemm1_h, cudaFuncAttributeMaxDynamicSharedMemorySize, G1_SMEM);
        cudaFuncSetAttribute(gemm2_h, cudaFuncAttributeMaxDynamicSharedMemorySize, G2_SMEM);
        attr_done = 1;
    }

    static void *p_xh = nullptr, *p_w1h, *p_w3h, *p_w2h;
    if (!p_xh) {
        cudaGetSymbolAddress(&p_xh, g_xh);
        cudaGetSymbolAddress(&p_w1h, g_w1h);
        cudaGetSymbolAddress(&p_w3h, g_w3h);
        cudaGetSymbolAddress(&p_w2h, g_w2h);
    }

    zero_cnt_kernel<<<1, 32>>>();
    f2h_all_kernel<<<(NCVT + 255) / 256, 256>>>(
        (const float4*)hidden, (const float4*)w1, (const float4*)w3, (const float4*)w2,
        (uint2*)p_xh, (uint2*)p_w1h, (uint2*)p_w3h, (uint2*)p_w2h);
    router_kernel<<<T_TOK / 8, 256>>>(hidden, gate_w, out + RL_OFFSET);
    // worst case one expert owns all NPAIR pairs; extra CTAs exit
    gemm1_h<<<dim3(F_DIM / 64, NPAIR / 256, N_EXP), 512, G1_SMEM>>>();
    gemm2_h<<<dim3(H_DIM / 256, NPAIR / 128, N_EXP), 512, G2_SMEM>>>();
    combine_kernel<<<(T_TOK * H_DIM / 4 + 255) / 256, 256>>>(out);
}

// round 16
// speedup vs baseline: 1.0563x; 1.0450x over previous
#include <cuda_runtime.h>
#include <cuda_fp16.h>
#include <math.h>
#include <stdint.h>

// Problem constants
#define T_TOK  8192
#define H_DIM  1024
#define F_DIM  2048
#define N_EXP  8
#define NPAIR  16384

#define OUT_ELEMS  (T_TOK * H_DIM)
#define RL_OFFSET  OUT_ELEMS

// ---------------- device scratch (static: allocation rules) ----------------
__device__ __half g_xh[(size_t)T_TOK * H_DIM];
__device__ __half g_w1h[(size_t)N_EXP * F_DIM * H_DIM];
__device__ __half g_w3h[(size_t)N_EXP * F_DIM * H_DIM];
__device__ __half g_w2h[(size_t)N_EXP * H_DIM * F_DIM];
__device__ __half g_gatedh[(size_t)NPAIR * F_DIM];
__device__ float  g_y[(size_t)NPAIR * H_DIM];
__device__ int    g_bucket[N_EXP * NPAIR];
__device__ int    g_cnt[N_EXP];
__device__ float  g_wpair[NPAIR];

// =================== PTX helpers (baseline sm_80-class PTX) ===================
__device__ __forceinline__ uint32_t smem_u32(const void* p) {
    uint32_t a;
    asm("{ .reg .u64 t; cvta.to.shared.u64 t, %1; cvt.u32.u64 %0, t; }" : "=r"(a) : "l"(p));
    return a;
}
#define CP16(dst, src) asm volatile("cp.async.cg.shared.global [%0], [%1], 16;" :: "r"(dst), "l"(src))
#define CPCOMMIT()     asm volatile("cp.async.commit_group;")
#define CPWAIT(n)      asm volatile("cp.async.wait_group %0;" :: "n"(n))

__device__ __forceinline__ void ldm_x4(uint32_t* r, uint32_t addr) {
    asm volatile("ldmatrix.sync.aligned.m8n8.x4.shared.b16 {%0,%1,%2,%3}, [%4];"
        : "=r"(r[0]), "=r"(r[1]), "=r"(r[2]), "=r"(r[3]) : "r"(addr));
}
__device__ __forceinline__ void mma16(float* c, const uint32_t* a, uint32_t b0, uint32_t b1) {
    asm volatile(
        "mma.sync.aligned.m16n8k16.row.col.f32.f16.f16.f32 "
        "{%0,%1,%2,%3}, {%4,%5,%6,%7}, {%8,%9}, {%0,%1,%2,%3};"
        : "+f"(c[0]), "+f"(c[1]), "+f"(c[2]), "+f"(c[3])
        : "r"(a[0]), "r"(a[1]), "r"(a[2]), "r"(a[3]), "r"(b0), "r"(b1));
}
// smem tile rows are 256B (128 halfs = BK chunk) = two 128B segments.
// phys(row, 16B-unit u in 0..15) = row*256 + (u>>3)*128 + (((u&7) ^ (row&7))<<4)
// -> conflict-free for cp.async and ldmatrix; all ldmatrix fragment rows
// satisfy (row&7) == (lane&7).

// =================== kernel 0: zero counters ===================
__global__ void zero_cnt_kernel() {
    if (threadIdx.x < N_EXP) g_cnt[threadIdx.x] = 0;
}

// =================== fused f32 -> f16 (rne) bulk convert ===================
#define NX4 ((T_TOK * H_DIM) / 4)
#define NW4 ((N_EXP * F_DIM * H_DIM) / 4)
#define NCVT (NX4 + 3 * NW4)

__global__ void f2h_all_kernel(const float4* __restrict__ x,
                               const float4* __restrict__ w1,
                               const float4* __restrict__ w3,
                               const float4* __restrict__ w2,
                               uint2* __restrict__ xh, uint2* __restrict__ w1h,
                               uint2* __restrict__ w3h, uint2* __restrict__ w2h) {
    int i = blockIdx.x * blockDim.x + threadIdx.x;
    if (i >= NCVT) return;
    const float4* s;
    uint2* d;
    int j;
    if (i < NX4)               { s = x;  d = xh;  j = i; }
    else if (i < NX4 + NW4)    { s = w1; d = w1h; j = i - NX4; }
    else if (i < NX4 + 2*NW4)  { s = w3; d = w3h; j = i - NX4 - NW4; }
    else                       { s = w2; d = w2h; j = i - NX4 - 2*NW4; }
    float4 v = s[j];
    __half2 h0 = __floats2half2_rn(v.x, v.y);
    __half2 h1 = __floats2half2_rn(v.z, v.w);
    uint2 o;
    o.x = *reinterpret_cast<uint32_t*>(&h0);
    o.y = *reinterpret_cast<uint32_t*>(&h1);
    d[j] = o;
}

// =================== kernel 1: router (f32, exact) ===================
__global__ void router_kernel(const float* __restrict__ x,
                              const float* __restrict__ gw,
                              float* __restrict__ rlogits) {
    int warp = (blockIdx.x * blockDim.x + threadIdx.x) >> 5;
    int lane = threadIdx.x & 31;
    if (warp >= T_TOK) return;

    const float* xr = x + (size_t)warp * H_DIM;
    float xv[32];
#pragma unroll
    for (int i = 0; i < 32; i++) xv[i] = xr[i * 32 + lane];

    float l[N_EXP];
#pragma unroll
    for (int e = 0; e < N_EXP; e++) {
        const float* g = gw + e * H_DIM;
        float s = 0.f;
#pragma unroll
        for (int i = 0; i < 32; i++) s += xv[i] * g[i * 32 + lane];
#pragma unroll
        for (int o = 16; o; o >>= 1) s += __shfl_xor_sync(0xffffffffu, s, o);
        l[e] = s;
    }

    if (lane == 0) {
#pragma unroll
        for (int e = 0; e < N_EXP; e++) rlogits[(size_t)warp * N_EXP + e] = l[e];

        int i0 = 0;
#pragma unroll
        for (int e = 1; e < N_EXP; e++) if (l[e] > l[i0]) i0 = e;
        int i1 = (i0 == 0) ? 1 : 0;
#pragma unroll
        for (int e = 0; e < N_EXP; e++) if (e != i0 && l[e] > l[i1]) i1 = e;

        float e1 = expf(l[i1] - l[i0]);
        float w0 = 1.f / (1.f + e1);
        float w1 = e1 / (1.f + e1);

        int p0 = warp * 2, p1 = warp * 2 + 1;
        g_wpair[p0] = w0;
        g_wpair[p1] = w1;
        int pos0 = atomicAdd(&g_cnt[i0], 1);
        g_bucket[i0 * NPAIR + pos0] = p0;
        int pos1 = atomicAdd(&g_cnt[i1], 1);
        g_bucket[i1 * NPAIR + pos1] = p1;
    }
}

// =================== kernel 2: GEMM1 fp16 (256x64, BK=128, 2-stage) =========
// CTA: 256 pairs x 64 F-cols. D1 = X W1^T, D3 = X W3^T, silu fuse -> g_gatedh.
// 512 threads = 16 warps (8m x 2n), warp tile 32x32 (dual accum).
// stage (96KB): A 256x256B @0, B1 64x256B @64K, B3 @80K. 2 stages, one sync
// per BK=128 chunk (8 chunks total).
#define G1_STAGE 98304
#define G1_SMEM  (1024 + 2 * G1_STAGE)
#define G1_NCH   (H_DIM / 128)   // 8

__global__ __launch_bounds__(512, 1) void gemm1_h() {
    int e = blockIdx.z;
    int nrows = g_cnt[e];
    int mbase = blockIdx.y * 256;
    if (mbase >= nrows) return;
    int fbase = blockIdx.x * 64;

    extern __shared__ char smem[];
    int* rowpair = (int*)smem;
    uint32_t sb = smem_u32(smem + 1024);

    int tid = threadIdx.x;
    int wid = tid >> 5, lane = tid & 31;
    int g = lane >> 2, tig = lane & 3;
    int wm = wid & 7, wn = wid >> 3;          // 8 x 2 warp grid

    if (tid < 256) {
        int r = mbase + tid;
        rowpair[tid] = (r < nrows) ? g_bucket[e * NPAIR + r] : -1;
    }
    __syncthreads();

    // cp.async mapping: per q, row rq = q*32 + trow, 16B unit u = tid&15
    int trow = tid >> 4, tu = tid & 15;
    // FIX (R15 bug): dst0 must include the tile-row offset trow*256
    uint32_t dst0 = (uint32_t)(trow * 256 + (tu >> 3) * 128 +
                               (((tu & 7) ^ (trow & 7)) << 4));
    const __half* aptr[8];
#pragma unroll
    for (int q = 0; q < 8; q++) {
        int rq = q * 32 + trow;
        int rp = rowpair[rq];
        int tok = ((rp >= 0) ? rp : rowpair[0]) >> 1;
        aptr[q] = g_xh + (size_t)tok * H_DIM + tu * 8;
    }
    const __half* b1p = g_w1h + ((size_t)e * F_DIM + fbase + trow) * H_DIM + tu * 8;
    const __half* b3p = g_w3h + ((size_t)e * F_DIM + fbase + trow) * H_DIM + tu * 8;

    auto load_chunk = [&](int c, int s) {
        uint32_t base = sb + s * G1_STAGE;
        int ko = c * 128;
#pragma unroll
        for (int q = 0; q < 8; q++)
            CP16(base + dst0 + q * 32 * 256, aptr[q] + ko);
#pragma unroll
        for (int q = 0; q < 2; q++) {
            CP16(base + 65536 + dst0 + q * 32 * 256, b1p + (size_t)q * 32 * H_DIM + ko);
            CP16(base + 81920 + dst0 + q * 32 * 256, b3p + (size_t)q * 32 * H_DIM + ko);
        }
        CPCOMMIT();
    };

    int lro = ((lane >> 3) & 1) * 8 + (lane & 7);
    int hi = lane >> 4;
    int s7 = lane & 7;

    uint32_t xoff[8];
#pragma unroll
    for (int kk = 0; kk < 8; kk++) {
        int u = kk * 2 + hi;
        xoff[kk] = (uint32_t)((u >> 3) * 128 + (((u & 7) ^ s7) << 4));
    }
    uint32_t aro[2], bro[2];
#pragma unroll
    for (int mf = 0; mf < 2; mf++) aro[mf] = (uint32_t)((wm * 32 + mf * 16 + lro) * 256);
#pragma unroll
    for (int j = 0; j < 2; j++)    bro[j]  = (uint32_t)((wn * 32 + j * 16 + lro) * 256);

    float acc1[2][4][4] = {}, acc3[2][4][4] = {};

    load_chunk(0, 0);
    for (int c = 0; c < G1_NCH; c++) {
        CPWAIT(0);                 // chunk c landed (all groups drained)
        __syncthreads();           // publish chunk c; stage (c+1)&1 free
        if (c + 1 < G1_NCH) load_chunk(c + 1, (c + 1) & 1);

        uint32_t aT = sb + (c & 1) * G1_STAGE;
#pragma unroll
        for (int kk = 0; kk < 8; kk++) {
            uint32_t aX  = aT + xoff[kk];
            uint32_t b1X = aX + 65536;
            uint32_t b3X = aX + 81920;
            uint32_t af[2][4];
#pragma unroll
            for (int mf = 0; mf < 2; mf++) ldm_x4(af[mf], aX + aro[mf]);
            uint32_t bf1[2][4], bf3[2][4];
#pragma unroll
            for (int j = 0; j < 2; j++) {
                ldm_x4(bf1[j], b1X + bro[j]);
                ldm_x4(bf3[j], b3X + bro[j]);
            }
#pragma unroll
            for (int mf = 0; mf < 2; mf++)
#pragma unroll
                for (int nf = 0; nf < 4; nf++) {
                    int j = nf >> 1, w = nf & 1;
                    mma16(acc1[mf][nf], af[mf], bf1[j][w], bf1[j][w + 2]);
                    mma16(acc3[mf][nf], af[mf], bf3[j][w], bf3[j][w + 2]);
                }
        }
    }

    // epilogue: silu(acc1)*acc3 -> g_gatedh (fp16)
#pragma unroll
    for (int mf = 0; mf < 2; mf++) {
#pragma unroll
        for (int hh = 0; hh < 2; hh++) {
            int row = wm * 32 + mf * 16 + g + hh * 8;
            int p = rowpair[row];
            if (p < 0) continue;
            __half* dst = g_gatedh + (size_t)p * F_DIM + fbase;
#pragma unroll
            for (int nf = 0; nf < 4; nf++) {
                int col = wn * 32 + nf * 8 + tig * 2;
                float c0 = acc1[mf][nf][hh * 2 + 0];
                float c1 = acc1[mf][nf][hh * 2 + 1];
                float g0 = acc3[mf][nf][hh * 2 + 0];
                float g1 = acc3[mf][nf][hh * 2 + 1];
                float o0 = c0 / (1.f + expf(-c0)) * g0;
                float o1 = c1 / (1.f + expf(-c1)) * g1;
                *(__half2*)(dst + col) = __floats2half2_rn(o0, o1);
            }
        }
    }
}

// =================== kernel 3: GEMM2 fp16 (128x256, BK=128, 2-stage) ========
// CTA: 128 pairs x 256 H-cols, K = F_DIM.
// 512 threads = 16 warps (4m x 4n), warp tile 32x64.
// stage (96KB): A 128x256B @0, B 256x256B @32K. 2 stages, one sync per chunk
// (16 chunks total).
#define G2_STAGE 98304
#define G2_SMEM  (1024 + 2 * G2_STAGE)
#define G2_NCH   (F_DIM / 128)   // 16

__global__ __launch_bounds__(512, 1) void gemm2_h() {
    int e = blockIdx.z;
    int nrows = g_cnt[e];
    int mbase = blockIdx.y * 128;
    if (mbase >= nrows) return;
    int hbase = blockIdx.x * 256;

    extern __shared__ char smem[];
    int* rowpair = (int*)smem;
    uint32_t sb = smem_u32(smem + 1024);

    int tid = threadIdx.x;
    int wid = tid >> 5, lane = tid & 31;
    int g = lane >> 2, tig = lane & 3;
    int wm = wid & 3, wn = wid >> 2;          // 4 x 4 warp grid

    if (tid < 128) {
        int r = mbase + tid;
        rowpair[tid] = (r < nrows) ? g_bucket[e * NPAIR + r] : -1;
    }
    __syncthreads();

    int trow = tid >> 4, tu = tid & 15;
    // FIX (R15 bug): dst0 must include the tile-row offset trow*256
    uint32_t dst0 = (uint32_t)(trow * 256 + (tu >> 3) * 128 +
                               (((tu & 7) ^ (trow & 7)) << 4));
    const __half* aptr[4];
#pragma unroll
    for (int q = 0; q < 4; q++) {
        int rq = q * 32 + trow;
        int rp = rowpair[rq];
        int pr = (rp >= 0) ? rp : rowpair[0];
        aptr[q] = g_gatedh + (size_t)pr * F_DIM + tu * 8;
    }
    const __half* bp = g_w2h + ((size_t)e * H_DIM + hbase + trow) * F_DIM + tu * 8;

    auto load_chunk = [&](int c, int s) {
        uint32_t base = sb + s * G2_STAGE;
        int ko = c * 128;
#pragma unroll
        for (int q = 0; q < 4; q++)
            CP16(base + dst0 + q * 32 * 256, aptr[q] + ko);
#pragma unroll
        for (int q = 0; q < 8; q++)
            CP16(base + 32768 + dst0 + q * 32 * 256, bp + (size_t)q * 32 * F_DIM + ko);
        CPCOMMIT();
    };

    int lro = ((lane >> 3) & 1) * 8 + (lane & 7);
    int hi = lane >> 4;
    int s7 = lane & 7;

    uint32_t xoff[8];
#pragma unroll
    for (int kk = 0; kk < 8; kk++) {
        int u = kk * 2 + hi;
        xoff[kk] = (uint32_t)((u >> 3) * 128 + (((u & 7) ^ s7) << 4));
    }
    uint32_t aro[2], bro[4];
#pragma unroll
    for (int mf = 0; mf < 2; mf++) aro[mf] = (uint32_t)((wm * 32 + mf * 16 + lro) * 256);
#pragma unroll
    for (int j = 0; j < 4; j++)    bro[j]  = (uint32_t)((wn * 64 + j * 16 + lro) * 256);

    float acc[2][8][4] = {};

    load_chunk(0, 0);
    for (int c = 0; c < G2_NCH; c++) {
        CPWAIT(0);
        __syncthreads();
        if (c + 1 < G2_NCH) load_chunk(c + 1, (c + 1) & 1);

        uint32_t aT = sb + (c & 1) * G2_STAGE;
#pragma unroll
        for (int kk = 0; kk < 8; kk++) {
            uint32_t aX = aT + xoff[kk];
            uint32_t bX = aX + 32768;
            uint32_t af[2][4];
#pragma unroll
            for (int mf = 0; mf < 2; mf++) ldm_x4(af[mf], aX + aro[mf]);
            uint32_t bf[4][4];
#pragma unroll
            for (int j = 0; j < 4; j++) ldm_x4(bf[j], bX + bro[j]);
#pragma unroll
            for (int mf = 0; mf < 2; mf++)
#pragma unroll
                for (int nf = 0; nf < 8; nf++) {
                    int j = nf >> 1, w = nf & 1;
                    mma16(acc[mf][nf], af[mf], bf[j][w], bf[j][w + 2]);
                }
        }
    }

#pragma unroll
    for (int mf = 0; mf < 2; mf++) {
#pragma unroll
        for (int hh = 0; hh < 2; hh++) {
            int row = wm * 32 + mf * 16 + g + hh * 8;
            int p = rowpair[row];
            if (p < 0) continue;
            float* dst = g_y + (size_t)p * H_DIM + hbase;
#pragma unroll
            for (int nf = 0; nf < 8; nf++) {
                int col = wn * 64 + nf * 8 + tig * 2;
                float2 o;
                o.x = acc[mf][nf][hh * 2 + 0];
                o.y = acc[mf][nf][hh * 2 + 1];
                *(float2*)(dst + col) = o;
            }
        }
    }
}

// =================== kernel 4: weighted combine ===================
__global__ void combine_kernel(float* __restrict__ out) {
    int idx = blockIdx.x * blockDim.x + threadIdx.x;
    if (idx >= T_TOK * H_DIM / 4) return;
    int t = idx / (H_DIM / 4);
    int h4 = idx - t * (H_DIM / 4);
    float w0 = g_wpair[2 * t];
    float w1 = g_wpair[2 * t + 1];
    float4 a = *(const float4*)(g_y + (size_t)(2 * t) * H_DIM + h4 * 4);
    float4 b = *(const float4*)(g_y + (size_t)(2 * t + 1) * H_DIM + h4 * 4);
    float4 o;
    o.x = w0 * a.x + w1 * b.x;
    o.y = w0 * a.y + w1 * b.y;
    o.z = w0 * a.z + w1 * b.z;
    o.w = w0 * a.w + w1 * b.w;
    ((float4*)out)[idx] = o;
}

// =================== launch ===================
extern "C" void kernel_launch(void* const* d_in, const int* in_sizes, int n_in,
                              void* d_out, int out_size) {
    const float* hidden = (const float*)d_in[0];
    const float* gate_w = (const float*)d_in[1];
    const float* w1     = (const float*)d_in[2];
    const float* w3     = (const float*)d_in[3];
    const float* w2     = (const float*)d_in[4];
    float* out = (float*)d_out;

    static int attr_done = 0;
    if (!attr_done) {
        cudaFuncSetAttribute(gemm1_h, cudaFuncAttributeMaxDynamicSharedMemorySize, G1_SMEM);
        cudaFuncSetAttribute(gemm2_h, cudaFuncAttributeMaxDynamicSharedMemorySize, G2_SMEM);
        attr_done = 1;
    }

    static void *p_xh = nullptr, *p_w1h, *p_w3h, *p_w2h;
    if (!p_xh) {
        cudaGetSymbolAddress(&p_xh, g_xh);
        cudaGetSymbolAddress(&p_w1h, g_w1h);
        cudaGetSymbolAddress(&p_w3h, g_w3h);
        cudaGetSymbolAddress(&p_w2h, g_w2h);
    }

    zero_cnt_kernel<<<1, 32>>>();
    f2h_all_kernel<<<(NCVT + 255) / 256, 256>>>(
        (const float4*)hidden, (const float4*)w1, (const float4*)w3, (const float4*)w2,
        (uint2*)p_xh, (uint2*)p_w1h, (uint2*)p_w3h, (uint2*)p_w2h);
    router_kernel<<<T_TOK / 8, 256>>>(hidden, gate_w, out + RL_OFFSET);
    // worst case one expert owns all NPAIR pairs; extra CTAs exit
    gemm1_h<<<dim3(F_DIM / 64, NPAIR / 256, N_EXP), 512, G1_SMEM>>>();
    gemm2_h<<<dim3(H_DIM / 256, NPAIR / 128, N_EXP), 512, G2_SMEM>>>();
    combine_kernel<<<(T_TOK * H_DIM / 4 + 255) / 256, 256>>>(out);
}